// round 10
// baseline (speedup 1.0000x reference)
#include <cuda_runtime.h>
#include <math_constants.h>

#define BATCH 16
#define NV    1024
#define NTOT  (BATCH * NV)
#define NBLK  888               // 6 blocks/SM * 148 SMs -> always one resident wave
#define NWARPS (NBLK * 8)

// Scratch (allocation-free: __device__ globals)
__device__ float4 g_cand[NTOT];  // {x, y, cos(psi), sin(psi)}
__device__ float  g_vel[NTOT];   // v

// ---------------------------------------------------------------------------
// Kernel 1: per-vehicle precompute. state layout: (B, NV*5)
// ---------------------------------------------------------------------------
__global__ void precompute_kernel(const float* __restrict__ state) {
    int t = blockIdx.x * blockDim.x + threadIdx.x;
    if (t >= NTOT) return;
    const float* s = state + (size_t)t * 5;
    float sn, cs;
    sincosf(s[3], &sn, &cs);
    g_cand[t] = make_float4(s[0], s[1], cs, sn);
    g_vel[t]  = s[2];
}

// ---------------------------------------------------------------------------
// Kernel 2: warp-per-ego, grid-stride over egos.
// ---------------------------------------------------------------------------
__global__ void __launch_bounds__(256) policy_kernel(
    const float* __restrict__ lengths,
    const float* __restrict__ v0p,
    const float* __restrict__ s0p,
    const float* __restrict__ dthp,
    const float* __restrict__ amaxp,
    const float* __restrict__ bp,
    float* __restrict__ out)
{
    const int lane  = threadIdx.x & 31;
    const int gwarp = (blockIdx.x * blockDim.x + threadIdx.x) >> 5;

    const float C20SQ = 0.8830222215594891f;   // cos^2(20 deg)
    const float C45   = 0.7071067811865476f;   // cos(45 deg)

    for (int ego = gwarp; ego < NTOT; ego += NWARPS) {
        const int bat  = ego >> 10;
        const int j    = ego & 1023;
        const int base = bat << 10;

        const float4 eg = g_cand[base + j];
        const float  vj = g_vel[base + j];
        const float xj = eg.x, yj = eg.y, cj = eg.z, sj = eg.w;

        float best = CUDART_INF_F;   // packed {proj_top22 | idx10}, min-reduced
        bool  stop = false;

        #pragma unroll 4
        for (int k = 0; k < NV / 32; ++k) {
            const int i = (k << 5) + lane;
            const float4 c4 = g_cand[base + i];

            const float dx  = c4.x - xj;
            const float dy  = c4.y - yj;
            const float dr2 = fmaf(dy, dy, dx * dx);
            const float proj = fmaf(dy, sj, dx * cj);     // ndist = dr*cos(delpsi)
            const float p2s  = proj * fabsf(proj);        // sign-folded proj^2

            // valid leader: proj>0 && proj^2 > dr2*cos^2(20)  (single compare)
            const bool pv = p2s > dr2 * C20SQ;
            const float key = __int_as_float((__float_as_int(proj) & ~1023) | i);
            best = fminf(best, pv ? key : CUDART_INF_F);

            // stop pairs need dr < 20 -- rare (~0.8%/pair); skip whole block
            if (__any_sync(0xffffffffu, dr2 < 400.0f)) {
                const float vi = g_vel[base + i];
                const float cosd = fmaf(c4.w, sj, c4.z * cj);  // cos(psi_i-psi_j)
                stop |= (dr2 < 400.0f) && (4.0f * p2s > dr2)   // folds proj>0 too
                        && (cosd < C45) && (vi > vj);
            }
        }

        // Warp reductions: packed key min (ties -> smaller index), any(stop)
        #pragma unroll
        for (int off = 16; off; off >>= 1)
            best = fminf(best, __shfl_xor_sync(0xffffffffu, best, off));
        stop = __any_sync(0xffffffffu, stop);

        if (lane == 0) {
            const float v0   = v0p[0];
            const float s0   = s0p[0];
            const float dth  = dthp[0];
            const float amax = amaxp[0];
            const float bb   = bp[0];

            const float t  = vj / v0;
            const float t2 = t * t;
            const float af = amax * (1.0f - t2 * t2);

            float action;
            if (stop) {
                action = af - amax;                      // ratio = 1
            } else if (isinf(best)) {
                action = af;                             // no leader
            } else {
                const int bidx = __float_as_int(best) & 1023;
                const float4 l4 = g_cand[base + bidx];
                const float  vl = g_vel[base + bidx];
                // recompute exact projection for the argmin leader
                const float proj = fmaf(l4.y - yj, sj, (l4.x - xj) * cj);
                const float sal  = proj - lengths[j];
                const float dvx = vl * l4.z - vj * cj;
                const float dvy = vl * l4.w - vj * sj;
                const float ndv = fmaf(dvy, sj, dvx * cj);   // dv*cos(vdelpsi)
                const float sstar = s0 + vj * dth
                                  + vj * ndv * (0.5f * rsqrtf(amax * bb));
                const float ratio = sstar / sal;
                action = af - amax * ratio * ratio;
            }
            out[base + j] = action;
        }
    }
}

// ---------------------------------------------------------------------------
// Inputs (metadata order): state, lengths, v0, s0, dth, amax, b
// ---------------------------------------------------------------------------
extern "C" void kernel_launch(void* const* d_in, const int* in_sizes, int n_in,
                              void* d_out, int out_size) {
    const float* state   = (const float*)d_in[0];
    const float* lengths = (const float*)d_in[1];
    const float* v0      = (const float*)d_in[2];
    const float* s0      = (const float*)d_in[3];
    const float* dth     = (const float*)d_in[4];
    const float* amax    = (const float*)d_in[5];
    const float* b       = (const float*)d_in[6];
    float* out = (float*)d_out;

    precompute_kernel<<<NTOT / 256, 256>>>(state);
    policy_kernel<<<NBLK, 256>>>(lengths, v0, s0, dth, amax, b, out);
}